// round 5
// baseline (speedup 1.0000x reference)
#include <cuda_runtime.h>
#include <math_constants.h>

#define BB 32
#define SS 2048
#define DD 512
#define CC 2
#define NSPLIT 32
#define TOK_PER_SPLIT (SS / NSPLIT)   // 64
#define WARPS 4
#define NTHREADS (WARPS * 32)         // 128
#define TOK_PER_WARP (TOK_PER_SPLIT / WARPS)  // 16

// scratch: per (batch, split): [m, l, acc[512]]
__device__ float g_partial[BB * NSPLIT * (DD + 2)];
__device__ unsigned int g_count[BB];   // zero-init; reset by last CTA each call

// ---------------------------------------------------------------------------
// Single fused kernel: split-K single-query flash attention + last-CTA
// reduction + classifier head. grid = (NSPLIT, BB), block = 128.
// ---------------------------------------------------------------------------
__global__ __launch_bounds__(NTHREADS, 6) void attn_fused_kernel(
    const void* __restrict__ tokens, const float* __restrict__ emb,
    const float* __restrict__ cls_w, const float* __restrict__ cls_b,
    float* __restrict__ out)
{
    const int split = blockIdx.x;
    const int b     = blockIdx.y;
    const int warp  = threadIdx.x >> 5;
    const int lane  = threadIdx.x & 31;

    // --- inline token-dtype detection (broadcast loads, ~free) ---
    // int64 tokens in [0,32000) have all-zero high words; 32 random int32
    // tokens cannot all be zero at odd word positions.
    const int* wdet = (const int*)tokens;
    int any = 0;
    #pragma unroll
    for (int i = 1; i < 64; i += 2) any |= (__ldg(&wdet[i]) != 0);
    const bool i32 = (any != 0);

    const int*       t32 = (const int*)tokens + (size_t)b * SS;
    const long long* t64 = (const long long*)tokens + (size_t)b * SS;

    // q = emb[tokens[b,0]]  (register fragment: 16 floats/lane)
    long long q_idx = i32 ? (long long)__ldg(&t32[0]) : __ldg(&t64[0]);
    const float4* qrow = (const float4*)(emb + q_idx * DD);
    float4 q[4];
    #pragma unroll
    for (int k = 0; k < 4; k++) q[k] = __ldg(&qrow[lane + k * 32]);

    float m = -CUDART_INF_F;
    float l = 0.0f;
    float4 acc[4];
    #pragma unroll
    for (int k = 0; k < 4; k++) acc[k] = make_float4(0.f, 0.f, 0.f, 0.f);

    const int t0 = split * TOK_PER_SPLIT + warp;

    // --- software-pipelined mainloop: prefetch row j+1 before computing j ---
    long long idx0 = i32 ? (long long)__ldg(&t32[t0]) : __ldg(&t64[t0]);
    const float4* row0 = (const float4*)(emb + idx0 * DD);
    float4 r[4];
    #pragma unroll
    for (int k = 0; k < 4; k++) r[k] = __ldg(&row0[lane + k * 32]);

    #pragma unroll 2
    for (int j = 0; j < TOK_PER_WARP; j++) {
        float4 rn[4];
        if (j + 1 < TOK_PER_WARP) {
            const int tn = t0 + (j + 1) * WARPS;
            long long idxn = i32 ? (long long)__ldg(&t32[tn]) : __ldg(&t64[tn]);
            const float4* rown = (const float4*)(emb + idxn * DD);
            #pragma unroll
            for (int k = 0; k < 4; k++) rn[k] = __ldg(&rown[lane + k * 32]);
        }

        float s = 0.0f;
        #pragma unroll
        for (int k = 0; k < 4; k++) {
            s += r[k].x * q[k].x + r[k].y * q[k].y
               + r[k].z * q[k].z + r[k].w * q[k].w;
        }
        #pragma unroll
        for (int o = 16; o > 0; o >>= 1) s += __shfl_xor_sync(0xffffffffu, s, o);

        const float m_new = fmaxf(m, s);
        const float fac   = __expf(m - m_new);   // exp(-inf)=0 on first iter
        const float w     = __expf(s - m_new);
        l = l * fac + w;
        #pragma unroll
        for (int k = 0; k < 4; k++) {
            acc[k].x = acc[k].x * fac + w * r[k].x;
            acc[k].y = acc[k].y * fac + w * r[k].y;
            acc[k].z = acc[k].z * fac + w * r[k].z;
            acc[k].w = acc[k].w * fac + w * r[k].w;
        }
        m = m_new;

        #pragma unroll
        for (int k = 0; k < 4; k++) r[k] = rn[k];
    }

    // --- combine the 4 warps' partials inside the CTA ---
    __shared__ float sh_m[WARPS];
    __shared__ float sh_l[WARPS];
    __shared__ float sh_acc[WARPS][DD];   // 8 KB

    if (lane == 0) { sh_m[warp] = m; sh_l[warp] = l; }
    #pragma unroll
    for (int k = 0; k < 4; k++) {
        const int base = k * 128 + lane * 4;
        sh_acc[warp][base + 0] = acc[k].x;
        sh_acc[warp][base + 1] = acc[k].y;
        sh_acc[warp][base + 2] = acc[k].z;
        sh_acc[warp][base + 3] = acc[k].w;
    }
    __syncthreads();

    float M = sh_m[0];
    #pragma unroll
    for (int w2 = 1; w2 < WARPS; w2++) M = fmaxf(M, sh_m[w2]);
    float facw[WARPS];
    float L = 0.0f;
    #pragma unroll
    for (int w2 = 0; w2 < WARPS; w2++) {
        facw[w2] = __expf(sh_m[w2] - M);
        L += sh_l[w2] * facw[w2];
    }

    float* outp = &g_partial[(b * NSPLIT + split) * (DD + 2)];
    for (int d = threadIdx.x; d < DD; d += NTHREADS) {
        float v = 0.0f;
        #pragma unroll
        for (int w2 = 0; w2 < WARPS; w2++) v += sh_acc[w2][d] * facw[w2];
        outp[2 + d] = v;
    }
    if (threadIdx.x == 0) { outp[0] = M; outp[1] = L; }

    // --- last-CTA-per-batch reduction + classifier head ---
    __threadfence();
    __shared__ unsigned int sh_is_last;
    if (threadIdx.x == 0) {
        unsigned int c = atomicAdd(&g_count[b], 1u);
        sh_is_last = (c == NSPLIT - 1) ? 1u : 0u;
    }
    __syncthreads();
    if (!sh_is_last) return;

    __threadfence();  // acquire-side: partials of all splits now visible
    const float* basep = &g_partial[b * NSPLIT * (DD + 2)];

    // split rescale factors live in SMEM so the reduce path doesn't inflate
    // the kernel's register allocation (max-over-paths).
    __shared__ float sh_ms[NSPLIT];
    __shared__ float sh_ls[NSPLIT];
    __shared__ float sh_fs[NSPLIT];
    __shared__ float sh_invL;
    if (threadIdx.x < NSPLIT) {
        sh_ms[threadIdx.x] = basep[threadIdx.x * (DD + 2) + 0];
        sh_ls[threadIdx.x] = basep[threadIdx.x * (DD + 2) + 1];
    }
    __syncthreads();
    if (threadIdx.x == 0) {
        float Mg = sh_ms[0];
        for (int s = 1; s < NSPLIT; s++) Mg = fmaxf(Mg, sh_ms[s]);
        float Lg = 0.0f;
        for (int s = 0; s < NSPLIT; s++) {
            float f = __expf(sh_ms[s] - Mg);
            sh_fs[s] = f;
            Lg += sh_ls[s] * f;
        }
        sh_invL = 1.0f / Lg;
    }
    __syncthreads();
    const float invL = sh_invL;

    float pd0 = 0.0f, pd1 = 0.0f;
    for (int d = threadIdx.x; d < DD; d += NTHREADS) {
        float v = 0.0f;
        #pragma unroll 8
        for (int s = 0; s < NSPLIT; s++) v += basep[s * (DD + 2) + 2 + d] * sh_fs[s];
        v *= invL;
        pd0 += v * __ldg(&cls_w[0 * DD + d]);
        pd1 += v * __ldg(&cls_w[1 * DD + d]);
    }
    #pragma unroll
    for (int o = 16; o > 0; o >>= 1) {
        pd0 += __shfl_xor_sync(0xffffffffu, pd0, o);
        pd1 += __shfl_xor_sync(0xffffffffu, pd1, o);
    }
    __shared__ float rw0[WARPS];
    __shared__ float rw1[WARPS];
    if (lane == 0) { rw0[warp] = pd0; rw1[warp] = pd1; }
    __syncthreads();
    if (threadIdx.x == 0) {
        float s0 = 0.0f, s1 = 0.0f;
        #pragma unroll
        for (int w2 = 0; w2 < WARPS; w2++) { s0 += rw0[w2]; s1 += rw1[w2]; }
        out[b * CC + 0] = s0 + __ldg(&cls_b[0]);
        out[b * CC + 1] = s1 + __ldg(&cls_b[1]);
        g_count[b] = 0u;   // reset for next call / graph replay
    }
}

// ---------------------------------------------------------------------------
extern "C" void kernel_launch(void* const* d_in, const int* in_sizes, int n_in,
                              void* d_out, int out_size) {
    (void)in_sizes; (void)n_in; (void)out_size;
    const void*  tokens = d_in[0];
    const float* emb    = (const float*)d_in[1];
    const float* cls_w  = (const float*)d_in[2];
    const float* cls_b  = (const float*)d_in[3];
    float* out = (float*)d_out;

    dim3 grid(NSPLIT, BB);
    attn_fused_kernel<<<grid, NTHREADS>>>(tokens, emb, cls_w, cls_b, out);
}

// round 6
// speedup vs baseline: 1.5158x; 1.5158x over previous
#include <cuda_runtime.h>
#include <math_constants.h>

#define BB 32
#define SS 2048
#define DD 512
#define CC 2
#define NSPLIT 16
#define TOK_PER_SPLIT (SS / NSPLIT)   // 128
#define WARPS 8
#define NTHREADS (WARPS * 32)         // 256

// scratch: per (batch, split): [m, l, acc[512]]
__device__ float g_partial[BB * NSPLIT * (DD + 2)];
__device__ unsigned int g_count[BB];   // zero-init; reset by last CTA each call

// ---------------------------------------------------------------------------
// Single fused kernel: split-K single-query flash attention + last-CTA
// reduction + classifier head. grid = (NSPLIT, BB), block = 256.
// ---------------------------------------------------------------------------
__global__ __launch_bounds__(NTHREADS, 4) void attn_fused_kernel(
    const void* __restrict__ tokens, const float* __restrict__ emb,
    const float* __restrict__ cls_w, const float* __restrict__ cls_b,
    float* __restrict__ out)
{
    const int split = blockIdx.x;
    const int b     = blockIdx.y;
    const int warp  = threadIdx.x >> 5;
    const int lane  = threadIdx.x & 31;

    // --- inline token-dtype detection (broadcast loads, ~free) ---
    // int64 tokens in [0,32000) have all-zero high words; 32 random int32
    // tokens cannot all be zero at odd word positions.
    const int* wdet = (const int*)tokens;
    int any = 0;
    #pragma unroll
    for (int i = 1; i < 64; i += 2) any |= (__ldg(&wdet[i]) != 0);
    const bool i32 = (any != 0);

    const int*       t32 = (const int*)tokens + (size_t)b * SS;
    const long long* t64 = (const long long*)tokens + (size_t)b * SS;

    // q = emb[tokens[b,0]]  (register fragment: 16 floats/lane)
    long long q_idx = i32 ? (long long)__ldg(&t32[0]) : __ldg(&t64[0]);
    const float4* qrow = (const float4*)(emb + q_idx * DD);
    float4 q[4];
    #pragma unroll
    for (int k = 0; k < 4; k++) q[k] = __ldg(&qrow[lane + k * 32]);

    float m = -1.0e30f;   // effectively -inf; __expf(-1e30) underflows to 0
    float l = 0.0f;
    float4 acc[4];
    #pragma unroll
    for (int k = 0; k < 4; k++) acc[k] = make_float4(0.f, 0.f, 0.f, 0.f);

    const int t0 = split * TOK_PER_SPLIT;
    for (int j = warp; j < TOK_PER_SPLIT; j += WARPS) {
        const int t = t0 + j;
        long long idx = i32 ? (long long)__ldg(&t32[t]) : __ldg(&t64[t]);
        const float4* row = (const float4*)(emb + idx * DD);
        float4 r[4];
        #pragma unroll
        for (int k = 0; k < 4; k++) r[k] = __ldg(&row[lane + k * 32]);

        float s = 0.0f;
        #pragma unroll
        for (int k = 0; k < 4; k++) {
            s += r[k].x * q[k].x + r[k].y * q[k].y
               + r[k].z * q[k].z + r[k].w * q[k].w;
        }
        #pragma unroll
        for (int o = 16; o > 0; o >>= 1) s += __shfl_xor_sync(0xffffffffu, s, o);

        // s is warp-uniform -> no divergence. Common path: no max update,
        // single FFMA per element. Rare path (~11x/2048): rescale, w==1.
        if (s <= m) {
            const float w = __expf(s - m);
            l += w;
            #pragma unroll
            for (int k = 0; k < 4; k++) {
                acc[k].x += w * r[k].x;
                acc[k].y += w * r[k].y;
                acc[k].z += w * r[k].z;
                acc[k].w += w * r[k].w;
            }
        } else {
            const float fac = __expf(m - s);   // first iter: __expf(-1e30)=0
            l = l * fac + 1.0f;
            #pragma unroll
            for (int k = 0; k < 4; k++) {
                acc[k].x = acc[k].x * fac + r[k].x;
                acc[k].y = acc[k].y * fac + r[k].y;
                acc[k].z = acc[k].z * fac + r[k].z;
                acc[k].w = acc[k].w * fac + r[k].w;
            }
            m = s;
        }
    }

    // --- combine the 8 warps' partials inside the CTA ---
    __shared__ float sh_m[WARPS];
    __shared__ float sh_l[WARPS];
    __shared__ float sh_acc[WARPS][DD];   // 16 KB

    if (lane == 0) { sh_m[warp] = m; sh_l[warp] = l; }
    #pragma unroll
    for (int k = 0; k < 4; k++) {
        const int base = k * 128 + lane * 4;
        sh_acc[warp][base + 0] = acc[k].x;
        sh_acc[warp][base + 1] = acc[k].y;
        sh_acc[warp][base + 2] = acc[k].z;
        sh_acc[warp][base + 3] = acc[k].w;
    }
    __syncthreads();

    float M = sh_m[0];
    #pragma unroll
    for (int w2 = 1; w2 < WARPS; w2++) M = fmaxf(M, sh_m[w2]);
    float facw[WARPS];
    float L = 0.0f;
    #pragma unroll
    for (int w2 = 0; w2 < WARPS; w2++) {
        facw[w2] = __expf(sh_m[w2] - M);
        L += sh_l[w2] * facw[w2];
    }

    float* outp = &g_partial[(b * NSPLIT + split) * (DD + 2)];
    for (int d = threadIdx.x; d < DD; d += NTHREADS) {
        float v = 0.0f;
        #pragma unroll
        for (int w2 = 0; w2 < WARPS; w2++) v += sh_acc[w2][d] * facw[w2];
        outp[2 + d] = v;
    }
    if (threadIdx.x == 0) { outp[0] = M; outp[1] = L; }

    // --- last-CTA-per-batch reduction + classifier head ---
    __threadfence();
    __shared__ unsigned int sh_is_last;
    if (threadIdx.x == 0) {
        unsigned int c = atomicAdd(&g_count[b], 1u);
        sh_is_last = (c == NSPLIT - 1) ? 1u : 0u;
    }
    __syncthreads();
    if (!sh_is_last) return;

    __threadfence();  // acquire-side: partials of all splits now visible
    const float* basep = &g_partial[b * NSPLIT * (DD + 2)];

    // split rescale factors live in SMEM so the reduce path doesn't inflate
    // the kernel's register allocation (max-over-paths).
    __shared__ float sh_ms[NSPLIT];
    __shared__ float sh_ls[NSPLIT];
    __shared__ float sh_fs[NSPLIT];
    __shared__ float sh_invL;
    if (threadIdx.x < NSPLIT) {
        sh_ms[threadIdx.x] = basep[threadIdx.x * (DD + 2) + 0];
        sh_ls[threadIdx.x] = basep[threadIdx.x * (DD + 2) + 1];
    }
    __syncthreads();
    if (threadIdx.x == 0) {
        float Mg = sh_ms[0];
        for (int s = 1; s < NSPLIT; s++) Mg = fmaxf(Mg, sh_ms[s]);
        float Lg = 0.0f;
        for (int s = 0; s < NSPLIT; s++) {
            float f = __expf(sh_ms[s] - Mg);
            sh_fs[s] = f;
            Lg += sh_ls[s] * f;
        }
        sh_invL = 1.0f / Lg;
    }
    __syncthreads();
    const float invL = sh_invL;

    float pd0 = 0.0f, pd1 = 0.0f;
    for (int d = threadIdx.x; d < DD; d += NTHREADS) {
        float v = 0.0f;
        #pragma unroll 8
        for (int s = 0; s < NSPLIT; s++) v += basep[s * (DD + 2) + 2 + d] * sh_fs[s];
        v *= invL;
        pd0 += v * __ldg(&cls_w[0 * DD + d]);
        pd1 += v * __ldg(&cls_w[1 * DD + d]);
    }
    #pragma unroll
    for (int o = 16; o > 0; o >>= 1) {
        pd0 += __shfl_xor_sync(0xffffffffu, pd0, o);
        pd1 += __shfl_xor_sync(0xffffffffu, pd1, o);
    }
    __shared__ float rw0[WARPS];
    __shared__ float rw1[WARPS];
    if (lane == 0) { rw0[warp] = pd0; rw1[warp] = pd1; }
    __syncthreads();
    if (threadIdx.x == 0) {
        float s0 = 0.0f, s1 = 0.0f;
        #pragma unroll
        for (int w2 = 0; w2 < WARPS; w2++) { s0 += rw0[w2]; s1 += rw1[w2]; }
        out[b * CC + 0] = s0 + __ldg(&cls_b[0]);
        out[b * CC + 1] = s1 + __ldg(&cls_b[1]);
        g_count[b] = 0u;   // reset for next call / graph replay
    }
}

// ---------------------------------------------------------------------------
extern "C" void kernel_launch(void* const* d_in, const int* in_sizes, int n_in,
                              void* d_out, int out_size) {
    (void)in_sizes; (void)n_in; (void)out_size;
    const void*  tokens = d_in[0];
    const float* emb    = (const float*)d_in[1];
    const float* cls_w  = (const float*)d_in[2];
    const float* cls_b  = (const float*)d_in[3];
    float* out = (float*)d_out;

    dim3 grid(NSPLIT, BB);
    attn_fused_kernel<<<grid, NTHREADS>>>(tokens, emb, cls_w, cls_b, out);
}